// round 8
// baseline (speedup 1.0000x reference)
#include <cuda_runtime.h>
#include <cuda_bf16.h>
#include <math.h>
#include <stdint.h>

// ---------------- problem constants ----------------
#define Bc    8
#define NAc   4096
#define NAAc  1024
#define NPCc  4096
#define Kc    16
#define KNCc  14
#define Gc    32
#define DAc   12
#define Fc    128
#define Dc    128
#define NATOM (Bc*NAc)      // 32768
#define NAAT  (Bc*NAAc)     // 8192
#define MDIM  (Gc*DAc)      // 384

// ---------------- scratch (device globals; no allocations allowed) ----------------
__device__ float g_center[NATOM*3];
__device__ float g_amat[NATOM*DAc];
__device__ float g_masky[NATOM];
__device__ __nv_bfloat16 g_Mh[(size_t)NATOM*MDIM];   // 25 MB
__device__ __nv_bfloat16 g_Ml[(size_t)NATOM*MDIM];   // 25 MB
__device__ __nv_bfloat16 g_yh[(size_t)NATOM*Fc];     // 8 MB
__device__ __nv_bfloat16 g_yl[(size_t)NATOM*Fc];     // 8 MB
__device__ __nv_bfloat16 g_Wnh[Fc*MDIM];             // W_nem^T hi [128 n][384 k]
__device__ __nv_bfloat16 g_Wnl[Fc*MDIM];
__device__ __nv_bfloat16 g_Wch[2*Dc*Fc];             // Wcat^T [256 n][128 k]
__device__ __nv_bfloat16 g_Wcl[2*Dc*Fc];
__device__ float g_af[(size_t)NATOM*2*Dc];           // 32 MB (att | feat)
__device__ float g_pooled[(size_t)NAAT*Dc];
__device__ float g_mean[Dc];
__device__ float g_inv[Dc];

// ---------------- helpers ----------------
__device__ __forceinline__ uint32_t smem_u32(const void* p) {
    uint32_t a;
    asm("{ .reg .u64 t; cvta.to.shared.u64 t, %1; cvt.u32.u64 %0, t; }" : "=r"(a) : "l"(p));
    return a;
}
__device__ __forceinline__ void split2(float f0, float f1, uint32_t& hi, uint32_t& lo)
{
    __nv_bfloat16 h0 = __float2bfloat16_rn(f0);
    __nv_bfloat16 h1 = __float2bfloat16_rn(f1);
    __nv_bfloat16 l0 = __float2bfloat16_rn(f0 - __bfloat162float(h0));
    __nv_bfloat16 l1 = __float2bfloat16_rn(f1 - __bfloat162float(h1));
    hi = ((uint32_t)__bfloat16_as_ushort(h1) << 16) | (uint32_t)__bfloat16_as_ushort(h0);
    lo = ((uint32_t)__bfloat16_as_ushort(l1) << 16) | (uint32_t)__bfloat16_as_ushort(l0);
}
__device__ __forceinline__ void mma_bf16(float* d, const uint32_t* a, const uint32_t* b)
{
    asm("mma.sync.aligned.m16n8k16.row.col.f32.bf16.bf16.f32 "
        "{%0,%1,%2,%3},{%4,%5,%6,%7},{%8,%9},{%0,%1,%2,%3};"
        : "+f"(d[0]), "+f"(d[1]), "+f"(d[2]), "+f"(d[3])
        : "r"(a[0]), "r"(a[1]), "r"(a[2]), "r"(a[3]), "r"(b[0]), "r"(b[1]));
}
#define LDSM_X4(r0, r1, r2, r3, addr) \
    asm volatile("ldmatrix.sync.aligned.m8n8.x4.shared.b16 {%0,%1,%2,%3}, [%4];" \
        : "=r"(r0), "=r"(r1), "=r"(r2), "=r"(r3) : "r"(addr))

// ---------------- K0: per-atom center / masked attributes ----------------
__global__ void k0_prep(const float* __restrict__ pc,
                        const float* __restrict__ mask_atom,
                        const float* __restrict__ attr_table,
                        const int*  __restrict__ frame_idx,
                        const int*  __restrict__ attr_idx)
{
    int t = blockIdx.x * blockDim.x + threadIdx.x;
    if (t >= NATOM) return;
    int b = t / NAc;
    int f1 = frame_idx[t*3 + 1];
    const float* p = pc + ((size_t)b*NPCc + f1)*3;
    g_center[t*3+0] = p[0];
    g_center[t*3+1] = p[1];
    g_center[t*3+2] = p[2];

    int ai = attr_idx[t];
    const float* arow = attr_table + (size_t)ai*DAc;
    float av[DAc];
    bool nz = false;
#pragma unroll
    for (int a = 0; a < DAc; a++) { av[a] = arow[a]; nz = nz || (av[a] != 0.0f); }
    float mattr = nz ? 1.0f : 0.0f;
#pragma unroll
    for (int a = 0; a < DAc; a++) g_amat[(size_t)t*DAc + a] = av[a]*mattr;
    g_masky[t] = mask_atom[t]*mattr;
}

// ---------------- Kw: transpose + split weights into [n][k] bf16 planes ----------------
__global__ void kWt(const float* __restrict__ Wnem,
                    const float* __restrict__ Watt, const float* __restrict__ Wfeat)
{
    int i = blockIdx.x * blockDim.x + threadIdx.x;
    if (i < Fc*MDIM) {
        int n = i / MDIM, k = i % MDIM;
        float f = Wnem[(size_t)k*Fc + n];
        __nv_bfloat16 h = __float2bfloat16_rn(f);
        g_Wnh[i] = h;
        g_Wnl[i] = __float2bfloat16_rn(f - __bfloat162float(h));
    } else if (i < Fc*MDIM + 2*Dc*Fc) {
        int j = i - Fc*MDIM;
        int n = j >> 7, k = j & 127;
        float f = (n < Dc) ? Watt[(size_t)k*Dc + n] : Wfeat[(size_t)k*Dc + (n - Dc)];
        __nv_bfloat16 h = __float2bfloat16_rn(f);
        g_Wch[j] = h;
        g_Wcl[j] = __float2bfloat16_rn(f - __bfloat162float(h));
    }
}

// ---------------- K1: per-atom M build, writes split bf16 planes ----------------
__global__ void k1_buildM(const float* __restrict__ pc,
                          const int*  __restrict__ frame_idx,
                          const int*  __restrict__ nb_idx,
                          const float* __restrict__ gauss)
{
    int warp = (blockIdx.x * blockDim.x + threadIdx.x) >> 5;
    int lane = threadIdx.x & 31;
    if (warp >= NATOM) return;
    int b = warp / NAc;
    const float* pcb = pc + (size_t)b*NPCc*3;

    int f0 = frame_idx[warp*3+0];
    int f1 = frame_idx[warp*3+1];
    int f2 = frame_idx[warp*3+2];

    const int4* nb4 = (const int4*)(nb_idx + (size_t)warp*Kc);
    int4 n0 = nb4[0], n1 = nb4[1], n2 = nb4[2], n3 = nb4[3];
    int nbi[Kc] = {n0.x,n0.y,n0.z,n0.w, n1.x,n1.y,n1.z,n1.w,
                   n2.x,n2.y,n2.z,n2.w, n3.x,n3.y,n3.z,n3.w};

    float cx = pcb[f1*3+0], cy = pcb[f1*3+1], cz = pcb[f1*3+2];

    float u1x = pcb[f2*3+0]-cx, u1y = pcb[f2*3+1]-cy, u1z = pcb[f2*3+2]-cz;
    float inv = 1.0f/(sqrtf(u1x*u1x+u1y*u1y+u1z*u1z)+1e-8f);
    u1x*=inv; u1y*=inv; u1z*=inv;

    float vx = pcb[f0*3+0]-cx, vy = pcb[f0*3+1]-cy, vz = pcb[f0*3+2]-cz;
    float dt = vx*u1x+vy*u1y+vz*u1z;
    float u2x = vx-dt*u1x, u2y = vy-dt*u1y, u2z = vz-dt*u1z;
    inv = 1.0f/(sqrtf(u2x*u2x+u2y*u2y+u2z*u2z)+1e-8f);
    u2x*=inv; u2y*=inv; u2z*=inv;

    float u3x = u1y*u2z-u1z*u2y;
    float u3y = u1z*u2x-u1x*u2z;
    float u3z = u1x*u2y-u1y*u2x;

    float gcx = gauss[lane*3+0], gcy = gauss[lane*3+1], gcz = gauss[lane*3+2];

    float acc[DAc];
#pragma unroll
    for (int a = 0; a < DAc; a++) acc[a] = 0.0f;

#pragma unroll
    for (int k = 0; k < Kc; k++) {
        int nbg = b*NAc + nbi[k];
        float dx = g_center[nbg*3+0]-cx;
        float dy = g_center[nbg*3+1]-cy;
        float dz = g_center[nbg*3+2]-cz;
        float r1 = u1x*dx+u1y*dy+u1z*dz;
        float r2 = u2x*dx+u2y*dy+u2z*dz;
        float r3 = u3x*dx+u3y*dy+u3z*dz;
        float t1 = r1-gcx, t2 = r2-gcy, t3 = r3-gcz;
        float gk = __expf(-0.5f*(t1*t1+t2*t2+t3*t3));
        const float4* am = (const float4*)(g_amat + (size_t)nbg*DAc);
        float4 A0 = am[0], A1 = am[1], A2 = am[2];
        acc[0]+=gk*A0.x; acc[1]+=gk*A0.y; acc[2]+=gk*A0.z; acc[3]+=gk*A0.w;
        acc[4]+=gk*A1.x; acc[5]+=gk*A1.y; acc[6]+=gk*A1.z; acc[7]+=gk*A1.w;
        acc[8]+=gk*A2.x; acc[9]+=gk*A2.y; acc[10]+=gk*A2.z; acc[11]+=gk*A2.w;
    }
    size_t off = (size_t)warp*MDIM + lane*DAc;
    uint32_t* dh = (uint32_t*)(g_Mh + off);
    uint32_t* dl = (uint32_t*)(g_Ml + off);
#pragma unroll
    for (int p = 0; p < 6; p++) {
        uint32_t h, l;
        split2(acc[2*p], acc[2*p+1], h, l);
        dh[p] = h;
        dl[p] = l;
    }
}

// ---------------- GEMM (bf16x3, mma.sync + ldmatrix, pre-split operands) ----------------
// C[128 x 128] tile = A @ B^T.  A planes [M][Kdim] bf16 hi/lo; B planes [N][Kdim] bf16 hi/lo.
// Smem tile layout: [row][k] bf16, row stride 24 elems (48 B) -> conflict-free ldmatrix.
// MODE 0: fp32 out C, scaled by maskrow*scale.  MODE 1: split bf16 out Yh/Yl [row][128].
#define PL   6144                  // plane bytes: 128 rows * 48 B
#define BUFB (4*PL)                // Ah|Al|Bh|Bl per buffer
template<int MODE>
__global__ __launch_bounds__(256, 2)
void gemm_lm(const __nv_bfloat16* __restrict__ Ahp, const __nv_bfloat16* __restrict__ Alp,
             const __nv_bfloat16* __restrict__ Bhp, const __nv_bfloat16* __restrict__ Blp,
             const float* __restrict__ maskrow,
             float* __restrict__ C, __nv_bfloat16* __restrict__ Yh, __nv_bfloat16* __restrict__ Yl,
             int Kdim, int ldc, float scale)
{
    extern __shared__ char sm[];
    uint32_t smb = smem_u32(sm);

    int tid = threadIdx.x, lane = tid & 31, wid = tid >> 5;
    int warp_m = wid >> 2;          // 0..1 -> m 0/64
    int warp_n = wid & 3;           // 0..3 -> n 0/32/64/96
    int row0 = blockIdx.x * 128, col0 = blockIdx.y * 128;
    int r4 = lane >> 2, c4 = lane & 3;

    // fill mapping: thread -> (row, k-half of 8)
    int frow = tid >> 1, fh = tid & 1;
    uint32_t fdst = (uint32_t)frow*48 + (uint32_t)fh*16;
    const __nv_bfloat16* gAh = Ahp + (size_t)(row0 + frow)*Kdim + fh*8;
    const __nv_bfloat16* gAl = Alp + (size_t)(row0 + frow)*Kdim + fh*8;
    const __nv_bfloat16* gBh = Bhp + (size_t)(col0 + frow)*Kdim + fh*8;
    const __nv_bfloat16* gBl = Blp + (size_t)(col0 + frow)*Kdim + fh*8;

    // ldmatrix fragment addresses (byte offset within a plane)
    uint32_t aoff[4], boff[2];
#pragma unroll
    for (int i = 0; i < 4; i++)
        aoff[i] = (uint32_t)(warp_m*64 + i*16 + (lane & 15))*48 + (uint32_t)(lane >> 4)*16;
#pragma unroll
    for (int jp = 0; jp < 2; jp++)
        boff[jp] = (uint32_t)(warp_n*32 + jp*16 + ((lane >> 4) << 3) + (lane & 7))*48
                 + (uint32_t)((lane >> 3) & 1)*16;

    float acc[4][4][4];
#pragma unroll
    for (int i = 0; i < 4; i++)
#pragma unroll
        for (int j = 0; j < 4; j++)
#pragma unroll
            for (int e = 0; e < 4; e++) acc[i][j][e] = 0.0f;

    uint4 vAh, vAl, vBh, vBl;
    auto load_regs = [&](int kk) {
        vAh = *(const uint4*)(gAh + kk);
        vAl = *(const uint4*)(gAl + kk);
        vBh = *(const uint4*)(gBh + kk);
        vBl = *(const uint4*)(gBl + kk);
    };
    auto store_tile = [&](int buf) {
        char* p = sm + buf*BUFB;
        *(uint4*)(p + 0*PL + fdst) = vAh;
        *(uint4*)(p + 1*PL + fdst) = vAl;
        *(uint4*)(p + 2*PL + fdst) = vBh;
        *(uint4*)(p + 3*PL + fdst) = vBl;
    };

    int T = Kdim >> 4;
    load_regs(0);
    store_tile(0);
    __syncthreads();

    for (int t = 0; t < T; t++) {
        uint32_t base = smb + (uint32_t)(t & 1)*BUFB;
        if (t + 1 < T) load_regs((t + 1) << 4);

        uint32_t bh[4][2], bl[4][2];
#pragma unroll
        for (int jp = 0; jp < 2; jp++) {
            LDSM_X4(bh[2*jp][0], bh[2*jp][1], bh[2*jp+1][0], bh[2*jp+1][1], base + 2*PL + boff[jp]);
            LDSM_X4(bl[2*jp][0], bl[2*jp][1], bl[2*jp+1][0], bl[2*jp+1][1], base + 3*PL + boff[jp]);
        }
#pragma unroll
        for (int i = 0; i < 4; i++) {
            uint32_t ah[4], al[4];
            LDSM_X4(ah[0], ah[1], ah[2], ah[3], base + 0*PL + aoff[i]);
            LDSM_X4(al[0], al[1], al[2], al[3], base + 1*PL + aoff[i]);
#pragma unroll
            for (int j = 0; j < 4; j++) {
                mma_bf16(acc[i][j], ah, bh[j]);   // Ah*Bh
                mma_bf16(acc[i][j], ah, bl[j]);   // Ah*Bl
                mma_bf16(acc[i][j], al, bh[j]);   // Al*Bh
            }
        }
        __syncthreads();
        if (t + 1 < T) {
            store_tile((t + 1) & 1);
            __syncthreads();
        }
    }

    // epilogue
#pragma unroll
    for (int i = 0; i < 4; i++) {
        int rlo = row0 + warp_m*64 + i*16 + r4;
        float mlo = maskrow[rlo]   * scale;
        float mhi = maskrow[rlo+8] * scale;
#pragma unroll
        for (int j = 0; j < 4; j++) {
            int c = col0 + warp_n*32 + j*8 + c4*2;
            if (MODE == 0) {
                *(float2*)(C + (size_t)rlo*ldc + c)     = make_float2(acc[i][j][0]*mlo, acc[i][j][1]*mlo);
                *(float2*)(C + (size_t)(rlo+8)*ldc + c) = make_float2(acc[i][j][2]*mhi, acc[i][j][3]*mhi);
            } else {
                uint32_t h, l;
                split2(acc[i][j][0]*mlo, acc[i][j][1]*mlo, h, l);
                *(uint32_t*)((uint16_t*)Yh + (size_t)rlo*128 + c) = h;
                *(uint32_t*)((uint16_t*)Yl + (size_t)rlo*128 + c) = l;
                split2(acc[i][j][2]*mhi, acc[i][j][3]*mhi, h, l);
                *(uint32_t*)((uint16_t*)Yh + (size_t)(rlo+8)*128 + c) = h;
                *(uint32_t*)((uint16_t*)Yl + (size_t)(rlo+8)*128 + c) = l;
            }
        }
    }
}

// ---------------- K4: per-AA masked softmax pooling ----------------
__global__ void k4_pool(const int*  __restrict__ aa_nb_idx,
                        const int*  __restrict__ seq_idx_atom,
                        const int*  __restrict__ seq_idx_aa,
                        const float* __restrict__ mask_aa)
{
    int bm = blockIdx.x;            // 0..NAAT-1
    int b  = bm / NAAc;
    int d  = threadIdx.x;           // 0..127

    __shared__ int   s_ag[KNCc];
    __shared__ float s_gm[KNCc];
    __shared__ float s_mask[KNCc];

    if (d < KNCc) {
        int nb = aa_nb_idx[(size_t)bm*KNCc + d];
        int ag = b*NAc + nb;
        s_ag[d] = ag;
        float mnb = g_masky[ag];
        s_mask[d] = mnb;
        int sq = seq_idx_atom[ag];
        int sa = seq_idx_aa[bm];
        s_gm[d] = (sq == sa) ? mnb : 0.0f;
    }
    __syncthreads();

    float logit[KNCc];
    float mx = -3.0e38f;
#pragma unroll
    for (int k = 0; k < KNCc; k++) {
        float att = g_af[(size_t)s_ag[k]*(2*Dc) + d];
        float l = (s_mask[k] > 0.0f) ? att : -1.0e9f;
        logit[k] = l;
        mx = fmaxf(mx, l);
    }
    float e[KNCc];
    float se = 0.0f;
#pragma unroll
    for (int k = 0; k < KNCc; k++) { e[k] = __expf(logit[k]-mx); se += e[k]; }
    float inv_se = 1.0f/se;
    float w[KNCc];
    float sw = 0.0f;
#pragma unroll
    for (int k = 0; k < KNCc; k++) { w[k] = e[k]*inv_se*s_gm[k]; sw += w[k]; }
    float inv_den = 1.0f/(sw + 1e-8f);
    float pooled = 0.0f;
#pragma unroll
    for (int k = 0; k < KNCc; k++)
        pooled += (w[k]*inv_den) * g_af[(size_t)s_ag[k]*(2*Dc) + Dc + d];

    pooled *= mask_aa[bm];
    g_pooled[(size_t)bm*Dc + d] = pooled;
}

// ---------------- K5: masked batch-norm statistics ----------------
__global__ void k5_stats(const float* __restrict__ mask_aa)
{
    int d = blockIdx.x;             // 0..127
    int tid = threadIdx.x;          // 256
    float s0 = 0.0f, s1 = 0.0f, s2 = 0.0f;
    for (int r = tid; r < NAAT; r += 256) {
        float m = mask_aa[r];
        float p = g_pooled[(size_t)r*Dc + d];
        s0 += m;
        s1 += m*p;
        s2 += m*p*p;
    }
    __shared__ float sh0[256], sh1[256], sh2[256];
    sh0[tid] = s0; sh1[tid] = s1; sh2[tid] = s2;
    __syncthreads();
    for (int s = 128; s > 0; s >>= 1) {
        if (tid < s) {
            sh0[tid] += sh0[tid+s];
            sh1[tid] += sh1[tid+s];
            sh2[tid] += sh2[tid+s];
        }
        __syncthreads();
    }
    if (tid == 0) {
        float n = sh0[0] + 1e-8f;
        float mean = sh1[0]/n;
        float var = (sh2[0] - 2.0f*mean*sh1[0] + mean*mean*sh0[0])/n;
        g_mean[d] = mean;
        g_inv[d]  = rsqrtf(var + 1e-5f);
    }
}

// ---------------- K6: normalize + relu + write outputs ----------------
__global__ void k6_out(const float* __restrict__ gamma,
                       const float* __restrict__ beta,
                       const float* __restrict__ mask_aa,
                       float* __restrict__ out, int out_size)
{
    int idx = blockIdx.x * blockDim.x + threadIdx.x;
    const int total = NAAT*Dc;
    if (idx < total) {
        int d = idx & (Dc-1);
        int r = idx >> 7;
        float p = g_pooled[idx];
        float v = (gamma[d]*(p - g_mean[d])*g_inv[d] + beta[d]) * mask_aa[r];
        out[idx] = fmaxf(v, 0.0f);
    }
    if (idx < NAAT && total + idx < out_size) {
        out[total + idx] = mask_aa[idx];
    }
}

// ---------------- launch ----------------
#define GEMM_SMEM (2*BUFB)   // 49152 B

extern "C" void kernel_launch(void* const* d_in, const int* in_sizes, int n_in,
                              void* d_out, int out_size)
{
    const float* point_clouds  = (const float*)d_in[0];
    const float* mask_atom     = (const float*)d_in[1];
    const float* mask_aa       = (const float*)d_in[2];
    const float* attr_table    = (const float*)d_in[3];
    const float* gauss_centers = (const float*)d_in[4];
    const float* W_nem         = (const float*)d_in[5];
    const float* W_att         = (const float*)d_in[6];
    const float* W_feat        = (const float*)d_in[7];
    const float* bn_gamma      = (const float*)d_in[8];
    const float* bn_beta       = (const float*)d_in[9];
    const int*   frame_idx     = (const int*)d_in[10];
    const int*   attr_idx      = (const int*)d_in[11];
    const int*   nb_idx        = (const int*)d_in[12];
    const int*   seq_idx_atom  = (const int*)d_in[13];
    const int*   seq_idx_aa    = (const int*)d_in[14];
    const int*   aa_nb_idx     = (const int*)d_in[15];
    float* out = (float*)d_out;

    __nv_bfloat16 *pMh, *pMl, *pYh, *pYl, *pWnh, *pWnl, *pWch, *pWcl;
    float *pAF, *pMask;
    cudaGetSymbolAddress((void**)&pMh,  g_Mh);
    cudaGetSymbolAddress((void**)&pMl,  g_Ml);
    cudaGetSymbolAddress((void**)&pYh,  g_yh);
    cudaGetSymbolAddress((void**)&pYl,  g_yl);
    cudaGetSymbolAddress((void**)&pWnh, g_Wnh);
    cudaGetSymbolAddress((void**)&pWnl, g_Wnl);
    cudaGetSymbolAddress((void**)&pWch, g_Wch);
    cudaGetSymbolAddress((void**)&pWcl, g_Wcl);
    cudaGetSymbolAddress((void**)&pAF,  g_af);
    cudaGetSymbolAddress((void**)&pMask, g_masky);

    cudaFuncSetAttribute(gemm_lm<0>, cudaFuncAttributeMaxDynamicSharedMemorySize, GEMM_SMEM);
    cudaFuncSetAttribute(gemm_lm<1>, cudaFuncAttributeMaxDynamicSharedMemorySize, GEMM_SMEM);

    // K0 + weight prep
    k0_prep<<<(NATOM+255)/256, 256>>>(point_clouds, mask_atom, attr_table, frame_idx, attr_idx);
    kWt<<<(Fc*MDIM + 2*Dc*Fc + 255)/256, 256>>>(W_nem, W_att, W_feat);

    // K1: build M (split bf16 planes)
    k1_buildM<<<(NATOM*32)/256, 256>>>(point_clouds, frame_idx, nb_idx, gauss_centers);

    // GEMM1: y = (M @ W_nem)/K * mask -> split bf16 planes
    gemm_lm<1><<<dim3(NATOM/128, 1), 256, GEMM_SMEM>>>(
        pMh, pMl, pWnh, pWnl, pMask, nullptr, pYh, pYl, MDIM, 0, 1.0f/(float)Kc);

    // GEMM2: [att|feat] = (y @ Wcat) * mask -> fp32
    gemm_lm<0><<<dim3(NATOM/128, 2), 256, GEMM_SMEM>>>(
        pYh, pYl, pWch, pWcl, pMask, pAF, nullptr, nullptr, Fc, 2*Dc, 1.0f);

    // K4: pooled
    k4_pool<<<NAAT, Dc>>>(aa_nb_idx, seq_idx_atom, seq_idx_aa, mask_aa);

    // K5: batch-norm stats
    k5_stats<<<Dc, 256>>>(mask_aa);

    // K6: outputs
    k6_out<<<(NAAT*Dc + 255)/256, 256>>>(bn_gamma, bn_beta, mask_aa, out, out_size);
}

// round 9
// speedup vs baseline: 1.0794x; 1.0794x over previous
#include <cuda_runtime.h>
#include <cuda_bf16.h>
#include <math.h>
#include <stdint.h>

// ---------------- problem constants ----------------
#define Bc    8
#define NAc   4096
#define NAAc  1024
#define NPCc  4096
#define Kc    16
#define KNCc  14
#define Gc    32
#define DAc   12
#define Fc    128
#define Dc    128
#define NATOM (Bc*NAc)      // 32768
#define NAAT  (Bc*NAAc)     // 8192
#define MDIM  (Gc*DAc)      // 384

// ---------------- scratch (device globals; no allocations allowed) ----------------
__device__ float g_center[NATOM*3];
__device__ float g_amat[NATOM*DAc];
__device__ float g_masky[NATOM];
__device__ float g_M[(size_t)NATOM*MDIM];            // 48 MB
__device__ __nv_bfloat16 g_Wch[2*Dc*Fc];             // Wcat^T hi [256 n][128 k]
__device__ __nv_bfloat16 g_Wcl[2*Dc*Fc];
__device__ float g_af[(size_t)NATOM*2*Dc];           // 32 MB (att | feat)
__device__ float g_pooled[(size_t)NAAT*Dc];
__device__ float g_mean[Dc];
__device__ float g_inv[Dc];

// ---------------- helpers: bf16 split + mma ----------------
__device__ __forceinline__ void split2(float f0, float f1, uint32_t& hi, uint32_t& lo)
{
    __nv_bfloat16 h0 = __float2bfloat16_rn(f0);
    __nv_bfloat16 h1 = __float2bfloat16_rn(f1);
    __nv_bfloat16 l0 = __float2bfloat16_rn(f0 - __bfloat162float(h0));
    __nv_bfloat16 l1 = __float2bfloat16_rn(f1 - __bfloat162float(h1));
    hi = ((uint32_t)__bfloat16_as_ushort(h1) << 16) | (uint32_t)__bfloat16_as_ushort(h0);
    lo = ((uint32_t)__bfloat16_as_ushort(l1) << 16) | (uint32_t)__bfloat16_as_ushort(l0);
}
__device__ __forceinline__ void mma_bf16(float* d, const uint32_t* a, const uint32_t* b)
{
    asm("mma.sync.aligned.m16n8k16.row.col.f32.bf16.bf16.f32 "
        "{%0,%1,%2,%3},{%4,%5,%6,%7},{%8,%9},{%0,%1,%2,%3};"
        : "+f"(d[0]), "+f"(d[1]), "+f"(d[2]), "+f"(d[3])
        : "r"(a[0]), "r"(a[1]), "r"(a[2]), "r"(a[3]), "r"(b[0]), "r"(b[1]));
}

// ---------------- K0: per-atom center / masked attributes ----------------
__global__ void k0_prep(const float* __restrict__ pc,
                        const float* __restrict__ mask_atom,
                        const float* __restrict__ attr_table,
                        const int*  __restrict__ frame_idx,
                        const int*  __restrict__ attr_idx)
{
    int t = blockIdx.x * blockDim.x + threadIdx.x;
    if (t >= NATOM) return;
    int b = t / NAc;
    int f1 = frame_idx[t*3 + 1];
    const float* p = pc + ((size_t)b*NPCc + f1)*3;
    g_center[t*3+0] = p[0];
    g_center[t*3+1] = p[1];
    g_center[t*3+2] = p[2];

    int ai = attr_idx[t];
    const float* arow = attr_table + (size_t)ai*DAc;
    float av[DAc];
    bool nz = false;
#pragma unroll
    for (int a = 0; a < DAc; a++) { av[a] = arow[a]; nz = nz || (av[a] != 0.0f); }
    float mattr = nz ? 1.0f : 0.0f;
#pragma unroll
    for (int a = 0; a < DAc; a++) g_amat[(size_t)t*DAc + a] = av[a]*mattr;
    g_masky[t] = mask_atom[t]*mattr;
}

// ---------------- Kw: transpose + split Wcat into [n][k] bf16 planes ----------------
__global__ void kWt(const float* __restrict__ Watt, const float* __restrict__ Wfeat)
{
    int j = blockIdx.x * blockDim.x + threadIdx.x;   // 0 .. 256*128-1
    if (j >= 2*Dc*Fc) return;
    int n = j >> 7, k = j & 127;
    float f = (n < Dc) ? Watt[(size_t)k*Dc + n] : Wfeat[(size_t)k*Dc + (n - Dc)];
    __nv_bfloat16 h = __float2bfloat16_rn(f);
    g_Wch[j] = h;
    g_Wcl[j] = __float2bfloat16_rn(f - __bfloat162float(h));
}

// ---------------- K1: per-atom M[g,a] build (warp per atom, lane = gaussian) ----------------
__global__ void k1_buildM(const float* __restrict__ pc,
                          const int*  __restrict__ frame_idx,
                          const int*  __restrict__ nb_idx,
                          const float* __restrict__ gauss)
{
    int warp = (blockIdx.x * blockDim.x + threadIdx.x) >> 5;
    int lane = threadIdx.x & 31;
    if (warp >= NATOM) return;
    int b = warp / NAc;
    const float* pcb = pc + (size_t)b*NPCc*3;

    int f0 = frame_idx[warp*3+0];
    int f1 = frame_idx[warp*3+1];
    int f2 = frame_idx[warp*3+2];

    const int4* nb4 = (const int4*)(nb_idx + (size_t)warp*Kc);
    int4 n0 = nb4[0], n1 = nb4[1], n2 = nb4[2], n3 = nb4[3];
    int nbi[Kc] = {n0.x,n0.y,n0.z,n0.w, n1.x,n1.y,n1.z,n1.w,
                   n2.x,n2.y,n2.z,n2.w, n3.x,n3.y,n3.z,n3.w};

    float cx = pcb[f1*3+0], cy = pcb[f1*3+1], cz = pcb[f1*3+2];

    float u1x = pcb[f2*3+0]-cx, u1y = pcb[f2*3+1]-cy, u1z = pcb[f2*3+2]-cz;
    float inv = 1.0f/(sqrtf(u1x*u1x+u1y*u1y+u1z*u1z)+1e-8f);
    u1x*=inv; u1y*=inv; u1z*=inv;

    float vx = pcb[f0*3+0]-cx, vy = pcb[f0*3+1]-cy, vz = pcb[f0*3+2]-cz;
    float dt = vx*u1x+vy*u1y+vz*u1z;
    float u2x = vx-dt*u1x, u2y = vy-dt*u1y, u2z = vz-dt*u1z;
    inv = 1.0f/(sqrtf(u2x*u2x+u2y*u2y+u2z*u2z)+1e-8f);
    u2x*=inv; u2y*=inv; u2z*=inv;

    float u3x = u1y*u2z-u1z*u2y;
    float u3y = u1z*u2x-u1x*u2z;
    float u3z = u1x*u2y-u1y*u2x;

    float gcx = gauss[lane*3+0], gcy = gauss[lane*3+1], gcz = gauss[lane*3+2];

    float acc[DAc];
#pragma unroll
    for (int a = 0; a < DAc; a++) acc[a] = 0.0f;

#pragma unroll
    for (int k = 0; k < Kc; k++) {
        int nbg = b*NAc + nbi[k];
        float dx = g_center[nbg*3+0]-cx;
        float dy = g_center[nbg*3+1]-cy;
        float dz = g_center[nbg*3+2]-cz;
        float r1 = u1x*dx+u1y*dy+u1z*dz;
        float r2 = u2x*dx+u2y*dy+u2z*dz;
        float r3 = u3x*dx+u3y*dy+u3z*dz;
        float t1 = r1-gcx, t2 = r2-gcy, t3 = r3-gcz;
        float gk = __expf(-0.5f*(t1*t1+t2*t2+t3*t3));
        const float4* am = (const float4*)(g_amat + (size_t)nbg*DAc);
        float4 A0 = am[0], A1 = am[1], A2 = am[2];
        acc[0]+=gk*A0.x; acc[1]+=gk*A0.y; acc[2]+=gk*A0.z; acc[3]+=gk*A0.w;
        acc[4]+=gk*A1.x; acc[5]+=gk*A1.y; acc[6]+=gk*A1.z; acc[7]+=gk*A1.w;
        acc[8]+=gk*A2.x; acc[9]+=gk*A2.y; acc[10]+=gk*A2.z; acc[11]+=gk*A2.w;
    }
    float4* Mo = (float4*)(g_M + (size_t)warp*MDIM + lane*DAc);
    Mo[0] = make_float4(acc[0],acc[1],acc[2],acc[3]);
    Mo[1] = make_float4(acc[4],acc[5],acc[6],acc[7]);
    Mo[2] = make_float4(acc[8],acc[9],acc[10],acc[11]);
}

// ---------------- Fused GEMM (bf16x3): y = (M@Wnem)/K*mask ; af = (y@Wcat)*mask ----------
// Per CTA: 128-row tile. GEMM1 K=384 (R6 mainloop). y staged in smem as split bf16
// planes, then GEMM2 K=128 over two n-halves of Wcat; af written fp32.
// Dynamic smem layout (uint32 words):
//   [0)      Ah2 [2][8][136]
//   [2176)   Al2
//   [4352)   Bh2
//   [6528)   Bl2
//   [8704)   Yh  [64][136]
//   [17408)  Yl  [64][136]
#define O_AL 2176
#define O_BH 4352
#define O_BL 6528
#define O_YH 8704
#define O_YL 17408
#define FUSED_SMEM (26112*4)    // 104448 B

__global__ __launch_bounds__(256, 2)
void gemm_fused(const float* __restrict__ A,          // g_M [32768][384]
                const float* __restrict__ Wn,         // W_nem [384][128]
                const __nv_bfloat16* __restrict__ Wch,// [256][128]
                const __nv_bfloat16* __restrict__ Wcl,
                const float* __restrict__ maskrow,
                float* __restrict__ AF)               // [32768][256]
{
    extern __shared__ uint32_t sm[];
#define AH2(b,kp,x) sm[        (b)*1088 + (kp)*136 + (x)]
#define AL2(b,kp,x) sm[O_AL  + (b)*1088 + (kp)*136 + (x)]
#define BH2(b,kp,x) sm[O_BH  + (b)*1088 + (kp)*136 + (x)]
#define BL2(b,kp,x) sm[O_BL  + (b)*1088 + (kp)*136 + (x)]
#define YH(kp,x)    sm[O_YH  + (kp)*136 + (x)]
#define YL(kp,x)    sm[O_YL  + (kp)*136 + (x)]

    int tid  = threadIdx.x;
    int lane = tid & 31;
    int wid  = tid >> 5;
    int warp_m = wid >> 2;          // 0..1 -> m 0/64
    int warp_n = wid & 3;           // 0..3 -> n 0/32/64/96
    int row0 = blockIdx.x * 128;
    int r4 = lane >> 2, c4 = lane & 3;

    // A fill mapping
    int a_r = tid >> 2;             // 0..63 (+64)
    int a_c = (tid & 3) * 4;        // 0,4,8,12
    // B fill mapping
    int b_c  = tid & 127;
    int b_kg = tid >> 7;            // 0/1

    float4 av0, av1;
    float  bv[8];

    float acc[4][4][4];
#pragma unroll
    for (int i = 0; i < 4; i++)
#pragma unroll
        for (int j = 0; j < 4; j++)
#pragma unroll
            for (int e = 0; e < 4; e++) acc[i][j][e] = 0.0f;

    // ---------------- GEMM1 mainloop (K = 384) ----------------
    auto load_regs1 = [&](int kk) {
        av0 = *(const float4*)(A + (size_t)(row0 + a_r)*MDIM + kk + a_c);
        av1 = *(const float4*)(A + (size_t)(row0 + 64 + a_r)*MDIM + kk + a_c);
#pragma unroll
        for (int e = 0; e < 8; e++)
            bv[e] = Wn[(size_t)(kk + b_kg*8 + e)*Fc + b_c];
    };
    auto store_tile1 = [&](int buf) {
        int ac2 = a_c >> 1;
        uint32_t h, l;
        split2(av0.x, av0.y, h, l); AH2(buf, ac2,   a_r)    = h; AL2(buf, ac2,   a_r)    = l;
        split2(av0.z, av0.w, h, l); AH2(buf, ac2+1, a_r)    = h; AL2(buf, ac2+1, a_r)    = l;
        split2(av1.x, av1.y, h, l); AH2(buf, ac2,   a_r+64) = h; AL2(buf, ac2,   a_r+64) = l;
        split2(av1.z, av1.w, h, l); AH2(buf, ac2+1, a_r+64) = h; AL2(buf, ac2+1, a_r+64) = l;
#pragma unroll
        for (int p = 0; p < 4; p++) {
            split2(bv[2*p], bv[2*p+1], h, l);
            BH2(buf, b_kg*4 + p, b_c) = h;
            BL2(buf, b_kg*4 + p, b_c) = l;
        }
    };

    const int T1 = MDIM >> 4;       // 24
    load_regs1(0);
    store_tile1(0);
    __syncthreads();

    for (int t = 0; t < T1; t++) {
        int buf = t & 1;
        if (t + 1 < T1) load_regs1((t + 1) << 4);

        uint32_t bh[4][2], bl[4][2];
#pragma unroll
        for (int j = 0; j < 4; j++) {
            int n = warp_n*32 + j*8 + r4;
            bh[j][0] = BH2(buf, c4,   n);  bh[j][1] = BH2(buf, c4+4, n);
            bl[j][0] = BL2(buf, c4,   n);  bl[j][1] = BL2(buf, c4+4, n);
        }
#pragma unroll
        for (int i = 0; i < 4; i++) {
            int m = warp_m*64 + i*16 + r4;
            uint32_t ah[4], al[4];
            ah[0] = AH2(buf, c4,   m); ah[1] = AH2(buf, c4,   m+8);
            ah[2] = AH2(buf, c4+4, m); ah[3] = AH2(buf, c4+4, m+8);
            al[0] = AL2(buf, c4,   m); al[1] = AL2(buf, c4,   m+8);
            al[2] = AL2(buf, c4+4, m); al[3] = AL2(buf, c4+4, m+8);
#pragma unroll
            for (int j = 0; j < 4; j++) {
                mma_bf16(acc[i][j], ah, bh[j]);
                mma_bf16(acc[i][j], ah, bl[j]);
                mma_bf16(acc[i][j], al, bh[j]);
            }
        }
        __syncthreads();
        if (t + 1 < T1) {
            store_tile1((t + 1) & 1);
            __syncthreads();
        }
    }

    // ---------------- stage y (masked, scaled) into smem split planes ----------------
    const float inv_k = 1.0f/(float)Kc;
#pragma unroll
    for (int i = 0; i < 4; i++) {
        int rl = warp_m*64 + i*16 + r4;        // local row
        float mlo = maskrow[row0 + rl]     * inv_k;
        float mhi = maskrow[row0 + rl + 8] * inv_k;
#pragma unroll
        for (int j = 0; j < 4; j++) {
            int kp = warp_n*16 + j*4 + c4;     // 0..63
            uint32_t h, l;
            split2(acc[i][j][0]*mlo, acc[i][j][1]*mlo, h, l);
            YH(kp, rl) = h;  YL(kp, rl) = l;
            split2(acc[i][j][2]*mhi, acc[i][j][3]*mhi, h, l);
            YH(kp, rl+8) = h;  YL(kp, rl+8) = l;
        }
    }
    __syncthreads();

    // ---------------- GEMM2: af[:, nh*128 .. ] = y @ WcatT (K = 128) ----------------
    uint4 vWh, vWl;
    auto load_regs2 = [&](int kk, int nh) {
        size_t off = (size_t)(nh*128 + b_c)*Fc + kk + b_kg*8;
        vWh = *(const uint4*)(Wch + off);
        vWl = *(const uint4*)(Wcl + off);
    };
    auto store_tile2 = [&](int buf) {
        BH2(buf, b_kg*4+0, b_c) = vWh.x;  BL2(buf, b_kg*4+0, b_c) = vWl.x;
        BH2(buf, b_kg*4+1, b_c) = vWh.y;  BL2(buf, b_kg*4+1, b_c) = vWl.y;
        BH2(buf, b_kg*4+2, b_c) = vWh.z;  BL2(buf, b_kg*4+2, b_c) = vWl.z;
        BH2(buf, b_kg*4+3, b_c) = vWh.w;  BL2(buf, b_kg*4+3, b_c) = vWl.w;
    };

    for (int nh = 0; nh < 2; nh++) {
#pragma unroll
        for (int i = 0; i < 4; i++)
#pragma unroll
            for (int j = 0; j < 4; j++)
#pragma unroll
                for (int e = 0; e < 4; e++) acc[i][j][e] = 0.0f;

        load_regs2(0, nh);
        store_tile2(0);
        __syncthreads();

        const int T2 = Fc >> 4;     // 8
        for (int t = 0; t < T2; t++) {
            int buf = t & 1;
            if (t + 1 < T2) load_regs2((t + 1) << 4, nh);

            uint32_t bh[4][2], bl[4][2];
#pragma unroll
            for (int j = 0; j < 4; j++) {
                int n = warp_n*32 + j*8 + r4;
                bh[j][0] = BH2(buf, c4,   n);  bh[j][1] = BH2(buf, c4+4, n);
                bl[j][0] = BL2(buf, c4,   n);  bl[j][1] = BL2(buf, c4+4, n);
            }
            int kb = t*8;
#pragma unroll
            for (int i = 0; i < 4; i++) {
                int m = warp_m*64 + i*16 + r4;
                uint32_t ah[4], al[4];
                ah[0] = YH(kb + c4,   m); ah[1] = YH(kb + c4,   m+8);
                ah[2] = YH(kb + c4+4, m); ah[3] = YH(kb + c4+4, m+8);
                al[0] = YL(kb + c4,   m); al[1] = YL(kb + c4,   m+8);
                al[2] = YL(kb + c4+4, m); al[3] = YL(kb + c4+4, m+8);
#pragma unroll
                for (int j = 0; j < 4; j++) {
                    mma_bf16(acc[i][j], ah, bh[j]);
                    mma_bf16(acc[i][j], ah, bl[j]);
                    mma_bf16(acc[i][j], al, bh[j]);
                }
            }
            __syncthreads();
            if (t + 1 < T2) {
                store_tile2((t + 1) & 1);
                __syncthreads();
            }
        }

        // epilogue: af columns nh*128 + ...
#pragma unroll
        for (int i = 0; i < 4; i++) {
            int rlo = row0 + warp_m*64 + i*16 + r4;
            float mlo = maskrow[rlo];
            float mhi = maskrow[rlo+8];
#pragma unroll
            for (int j = 0; j < 4; j++) {
                int c = nh*128 + warp_n*32 + j*8 + c4*2;
                *(float2*)(AF + (size_t)rlo*(2*Dc) + c)     = make_float2(acc[i][j][0]*mlo, acc[i][j][1]*mlo);
                *(float2*)(AF + (size_t)(rlo+8)*(2*Dc) + c) = make_float2(acc[i][j][2]*mhi, acc[i][j][3]*mhi);
            }
        }
    }
#undef AH2
#undef AL2
#undef BH2
#undef BL2
#undef YH
#undef YL
}

// ---------------- K4: per-AA masked softmax pooling ----------------
__global__ void k4_pool(const int*  __restrict__ aa_nb_idx,
                        const int*  __restrict__ seq_idx_atom,
                        const int*  __restrict__ seq_idx_aa,
                        const float* __restrict__ mask_aa)
{
    int bm = blockIdx.x;            // 0..NAAT-1
    int b  = bm / NAAc;
    int d  = threadIdx.x;           // 0..127

    __shared__ int   s_ag[KNCc];
    __shared__ float s_gm[KNCc];
    __shared__ float s_mask[KNCc];

    if (d < KNCc) {
        int nb = aa_nb_idx[(size_t)bm*KNCc + d];
        int ag = b*NAc + nb;
        s_ag[d] = ag;
        float mnb = g_masky[ag];
        s_mask[d] = mnb;
        int sq = seq_idx_atom[ag];
        int sa = seq_idx_aa[bm];
        s_gm[d] = (sq == sa) ? mnb : 0.0f;
    }
    __syncthreads();

    float logit[KNCc];
    float mx = -3.0e38f;
#pragma unroll
    for (int k = 0; k < KNCc; k++) {
        float att = g_af[(size_t)s_ag[k]*(2*Dc) + d];
        float l = (s_mask[k] > 0.0f) ? att : -1.0e9f;
        logit[k] = l;
        mx = fmaxf(mx, l);
    }
    float e[KNCc];
    float se = 0.0f;
#pragma unroll
    for (int k = 0; k < KNCc; k++) { e[k] = __expf(logit[k]-mx); se += e[k]; }
    float inv_se = 1.0f/se;
    float w[KNCc];
    float sw = 0.0f;
#pragma unroll
    for (int k = 0; k < KNCc; k++) { w[k] = e[k]*inv_se*s_gm[k]; sw += w[k]; }
    float inv_den = 1.0f/(sw + 1e-8f);
    float pooled = 0.0f;
#pragma unroll
    for (int k = 0; k < KNCc; k++)
        pooled += (w[k]*inv_den) * g_af[(size_t)s_ag[k]*(2*Dc) + Dc + d];

    pooled *= mask_aa[bm];
    g_pooled[(size_t)bm*Dc + d] = pooled;
}

// ---------------- K5: masked batch-norm statistics ----------------
__global__ void k5_stats(const float* __restrict__ mask_aa)
{
    int d = blockIdx.x;             // 0..127
    int tid = threadIdx.x;          // 256
    float s0 = 0.0f, s1 = 0.0f, s2 = 0.0f;
    for (int r = tid; r < NAAT; r += 256) {
        float m = mask_aa[r];
        float p = g_pooled[(size_t)r*Dc + d];
        s0 += m;
        s1 += m*p;
        s2 += m*p*p;
    }
    __shared__ float sh0[256], sh1[256], sh2[256];
    sh0[tid] = s0; sh1[tid] = s1; sh2[tid] = s2;
    __syncthreads();
    for (int s = 128; s > 0; s >>= 1) {
        if (tid < s) {
            sh0[tid] += sh0[tid+s];
            sh1[tid] += sh1[tid+s];
            sh2[tid] += sh2[tid+s];
        }
        __syncthreads();
    }
    if (tid == 0) {
        float n = sh0[0] + 1e-8f;
        float mean = sh1[0]/n;
        float var = (sh2[0] - 2.0f*mean*sh1[0] + mean*mean*sh0[0])/n;
        g_mean[d] = mean;
        g_inv[d]  = rsqrtf(var + 1e-5f);
    }
}

// ---------------- K6: normalize + relu + write outputs ----------------
__global__ void k6_out(const float* __restrict__ gamma,
                       const float* __restrict__ beta,
                       const float* __restrict__ mask_aa,
                       float* __restrict__ out, int out_size)
{
    int idx = blockIdx.x * blockDim.x + threadIdx.x;
    const int total = NAAT*Dc;
    if (idx < total) {
        int d = idx & (Dc-1);
        int r = idx >> 7;
        float p = g_pooled[idx];
        float v = (gamma[d]*(p - g_mean[d])*g_inv[d] + beta[d]) * mask_aa[r];
        out[idx] = fmaxf(v, 0.0f);
    }
    if (idx < NAAT && total + idx < out_size) {
        out[total + idx] = mask_aa[idx];
    }
}

// ---------------- launch ----------------
extern "C" void kernel_launch(void* const* d_in, const int* in_sizes, int n_in,
                              void* d_out, int out_size)
{
    const float* point_clouds  = (const float*)d_in[0];
    const float* mask_atom     = (const float*)d_in[1];
    const float* mask_aa       = (const float*)d_in[2];
    const float* attr_table    = (const float*)d_in[3];
    const float* gauss_centers = (const float*)d_in[4];
    const float* W_nem         = (const float*)d_in[5];
    const float* W_att         = (const float*)d_in[6];
    const float* W_feat        = (const float*)d_in[7];
    const float* bn_gamma      = (const float*)d_in[8];
    const float* bn_beta       = (const float*)d_in[9];
    const int*   frame_idx     = (const int*)d_in[10];
    const int*   attr_idx      = (const int*)d_in[11];
    const int*   nb_idx        = (const int*)d_in[12];
    const int*   seq_idx_atom  = (const int*)d_in[13];
    const int*   seq_idx_aa    = (const int*)d_in[14];
    const int*   aa_nb_idx     = (const int*)d_in[15];
    float* out = (float*)d_out;

    float *pM, *pAF, *pMask;
    __nv_bfloat16 *pWch, *pWcl;
    cudaGetSymbolAddress((void**)&pM,   g_M);
    cudaGetSymbolAddress((void**)&pAF,  g_af);
    cudaGetSymbolAddress((void**)&pMask, g_masky);
    cudaGetSymbolAddress((void**)&pWch, g_Wch);
    cudaGetSymbolAddress((void**)&pWcl, g_Wcl);

    cudaFuncSetAttribute(gemm_fused, cudaFuncAttributeMaxDynamicSharedMemorySize, FUSED_SMEM);

    // K0 + weight prep
    k0_prep<<<(NATOM+255)/256, 256>>>(point_clouds, mask_atom, attr_table, frame_idx, attr_idx);
    kWt<<<(2*Dc*Fc+255)/256, 256>>>(W_att, W_feat);

    // K1: build M
    k1_buildM<<<(NATOM*32)/256, 256>>>(point_clouds, frame_idx, nb_idx, gauss_centers);

    // Fused GEMM1+GEMM2
    gemm_fused<<<NATOM/128, 256, FUSED_SMEM>>>(pM, W_nem, pWch, pWcl, pMask, pAF);

    // K4: pooled
    k4_pool<<<NAAT, Dc>>>(aa_nb_idx, seq_idx_atom, seq_idx_aa, mask_aa);

    // K5: batch-norm stats
    k5_stats<<<Dc, 256>>>(mask_aa);

    // K6: outputs
    k6_out<<<(NAAT*Dc + 255)/256, 256>>>(bn_gamma, bn_beta, mask_aa, out, out_size);
}

// round 10
// speedup vs baseline: 1.1140x; 1.0321x over previous
#include <cuda_runtime.h>
#include <cuda_bf16.h>
#include <math.h>
#include <stdint.h>

// ---------------- problem constants ----------------
#define Bc    8
#define NAc   4096
#define NAAc  1024
#define NPCc  4096
#define Kc    16
#define KNCc  14
#define Gc    32
#define DAc   12
#define Fc    128
#define Dc    128
#define NATOM (Bc*NAc)      // 32768
#define NAAT  (Bc*NAAc)     // 8192
#define MDIM  (Gc*DAc)      // 384

// ---------------- scratch (device globals; no allocations allowed) ----------------
__device__ float g_center[NATOM*3];
__device__ float g_amat[NATOM*DAc];
__device__ float g_masky[NATOM];
__device__ float g_M[(size_t)NATOM*MDIM];            // 48 MB
__device__ __nv_bfloat16 g_Wch[2*Dc*Fc];             // Wcat^T hi [256 n][128 k]
__device__ __nv_bfloat16 g_Wcl[2*Dc*Fc];
__device__ float g_af[(size_t)NATOM*2*Dc];           // 32 MB (att | feat)
__device__ float g_pooled[(size_t)NAAT*Dc];
__device__ float g_mean[Dc];
__device__ float g_inv[Dc];

// ---------------- helpers ----------------
__device__ __forceinline__ void split2(float f0, float f1, uint32_t& hi, uint32_t& lo)
{
    __nv_bfloat16 h0 = __float2bfloat16_rn(f0);
    __nv_bfloat16 h1 = __float2bfloat16_rn(f1);
    __nv_bfloat16 l0 = __float2bfloat16_rn(f0 - __bfloat162float(h0));
    __nv_bfloat16 l1 = __float2bfloat16_rn(f1 - __bfloat162float(h1));
    hi = ((uint32_t)__bfloat16_as_ushort(h1) << 16) | (uint32_t)__bfloat16_as_ushort(h0);
    lo = ((uint32_t)__bfloat16_as_ushort(l1) << 16) | (uint32_t)__bfloat16_as_ushort(l0);
}
__device__ __forceinline__ void mma_bf16(float* d, const uint32_t* a, const uint32_t* b)
{
    asm("mma.sync.aligned.m16n8k16.row.col.f32.bf16.bf16.f32 "
        "{%0,%1,%2,%3},{%4,%5,%6,%7},{%8,%9},{%0,%1,%2,%3};"
        : "+f"(d[0]), "+f"(d[1]), "+f"(d[2]), "+f"(d[3])
        : "r"(a[0]), "r"(a[1]), "r"(a[2]), "r"(a[3]), "r"(b[0]), "r"(b[1]));
}
// packed dual-FMA (FFMA2): d = a*b + d  (two independent rn fp32 FMAs)
#define FMA2(d, a, b) \
    asm("fma.rn.f32x2 %0, %1, %2, %3;" : "+l"(d) : "l"(a), "l"(b), "l"(d))

// ---------------- K0: per-atom center / masked attributes ----------------
__global__ void k0_prep(const float* __restrict__ pc,
                        const float* __restrict__ mask_atom,
                        const float* __restrict__ attr_table,
                        const int*  __restrict__ frame_idx,
                        const int*  __restrict__ attr_idx)
{
    int t = blockIdx.x * blockDim.x + threadIdx.x;
    if (t >= NATOM) return;
    int b = t / NAc;
    int f1 = frame_idx[t*3 + 1];
    const float* p = pc + ((size_t)b*NPCc + f1)*3;
    g_center[t*3+0] = p[0];
    g_center[t*3+1] = p[1];
    g_center[t*3+2] = p[2];

    int ai = attr_idx[t];
    const float* arow = attr_table + (size_t)ai*DAc;
    float av[DAc];
    bool nz = false;
#pragma unroll
    for (int a = 0; a < DAc; a++) { av[a] = arow[a]; nz = nz || (av[a] != 0.0f); }
    float mattr = nz ? 1.0f : 0.0f;
#pragma unroll
    for (int a = 0; a < DAc; a++) g_amat[(size_t)t*DAc + a] = av[a]*mattr;
    g_masky[t] = mask_atom[t]*mattr;
}

// ---------------- Kw: transpose + split Wcat into [n][k] bf16 planes ----------------
__global__ void kWt(const float* __restrict__ Watt, const float* __restrict__ Wfeat)
{
    int j = blockIdx.x * blockDim.x + threadIdx.x;   // 0 .. 256*128-1
    if (j >= 2*Dc*Fc) return;
    int n = j >> 7, k = j & 127;
    float f = (n < Dc) ? Watt[(size_t)k*Dc + n] : Wfeat[(size_t)k*Dc + (n - Dc)];
    __nv_bfloat16 h = __float2bfloat16_rn(f);
    g_Wch[j] = h;
    g_Wcl[j] = __float2bfloat16_rn(f - __bfloat162float(h));
}

// ---------------- K1: per-atom M build (warp per atom, lane = gaussian) ----------------
// Lane k<16 precomputes neighbor-k local coords; broadcast via shfl.
// Accumulation in packed f32x2 (FFMA2) — bitwise identical to scalar rn FMA.
__global__ void k1_buildM(const float* __restrict__ pc,
                          const int*  __restrict__ frame_idx,
                          const int*  __restrict__ nb_idx,
                          const float* __restrict__ gauss)
{
    int warp = (blockIdx.x * blockDim.x + threadIdx.x) >> 5;
    int lane = threadIdx.x & 31;
    if (warp >= NATOM) return;
    int b = warp / NAc;
    const float* pcb = pc + (size_t)b*NPCc*3;

    int f0 = frame_idx[warp*3+0];
    int f1 = frame_idx[warp*3+1];
    int f2 = frame_idx[warp*3+2];

    float cx = pcb[f1*3+0], cy = pcb[f1*3+1], cz = pcb[f1*3+2];

    float u1x = pcb[f2*3+0]-cx, u1y = pcb[f2*3+1]-cy, u1z = pcb[f2*3+2]-cz;
    float inv = 1.0f/(sqrtf(u1x*u1x+u1y*u1y+u1z*u1z)+1e-8f);
    u1x*=inv; u1y*=inv; u1z*=inv;

    float vx = pcb[f0*3+0]-cx, vy = pcb[f0*3+1]-cy, vz = pcb[f0*3+2]-cz;
    float dt = vx*u1x+vy*u1y+vz*u1z;
    float u2x = vx-dt*u1x, u2y = vy-dt*u1y, u2z = vz-dt*u1z;
    inv = 1.0f/(sqrtf(u2x*u2x+u2y*u2y+u2z*u2z)+1e-8f);
    u2x*=inv; u2y*=inv; u2z*=inv;

    float u3x = u1y*u2z-u1z*u2y;
    float u3y = u1z*u2x-u1x*u2z;
    float u3z = u1x*u2y-u1y*u2x;

    // lane k < 16: gather neighbor-k center, rotate to local frame
    int nbg_l = 0;
    float r1 = 0.0f, r2 = 0.0f, r3 = 0.0f;
    if (lane < Kc) {
        nbg_l = b*NAc + nb_idx[(size_t)warp*Kc + lane];
        float dx = g_center[nbg_l*3+0]-cx;
        float dy = g_center[nbg_l*3+1]-cy;
        float dz = g_center[nbg_l*3+2]-cz;
        r1 = u1x*dx+u1y*dy+u1z*dz;
        r2 = u2x*dx+u2y*dy+u2z*dz;
        r3 = u3x*dx+u3y*dy+u3z*dz;
    }

    float gcx = gauss[lane*3+0], gcy = gauss[lane*3+1], gcz = gauss[lane*3+2];

    unsigned long long acc2[6];
#pragma unroll
    for (int p = 0; p < 6; p++) acc2[p] = 0ull;

    const float NHL2E = -0.72134752044448170368f;   // -0.5 * log2(e)

#pragma unroll
    for (int k = 0; k < Kc; k++) {
        int   nbg = __shfl_sync(0xffffffffu, nbg_l, k);
        float t1  = __shfl_sync(0xffffffffu, r1, k) - gcx;
        float t2  = __shfl_sync(0xffffffffu, r2, k) - gcy;
        float t3  = __shfl_sync(0xffffffffu, r3, k) - gcz;
        float d2  = fmaf(t3, t3, fmaf(t2, t2, t1*t1));
        float gk;
        asm("ex2.approx.f32 %0, %1;" : "=f"(gk) : "f"(d2 * NHL2E));
        unsigned long long gk2;
        asm("mov.b64 %0, {%1, %1};" : "=l"(gk2) : "f"(gk));
        const ulonglong2* am = (const ulonglong2*)(g_amat + (size_t)nbg*DAc);
        ulonglong2 A0 = am[0], A1 = am[1], A2 = am[2];
        FMA2(acc2[0], gk2, A0.x);  FMA2(acc2[1], gk2, A0.y);
        FMA2(acc2[2], gk2, A1.x);  FMA2(acc2[3], gk2, A1.y);
        FMA2(acc2[4], gk2, A2.x);  FMA2(acc2[5], gk2, A2.y);
    }

    float o[12];
#pragma unroll
    for (int p = 0; p < 6; p++)
        asm("mov.b64 {%0, %1}, %2;" : "=f"(o[2*p]), "=f"(o[2*p+1]) : "l"(acc2[p]));
    float4* Mo = (float4*)(g_M + (size_t)warp*MDIM + lane*DAc);
    Mo[0] = make_float4(o[0], o[1], o[2],  o[3]);
    Mo[1] = make_float4(o[4], o[5], o[6],  o[7]);
    Mo[2] = make_float4(o[8], o[9], o[10], o[11]);
}

// ---------------- Fused GEMM (bf16x3): y = (M@Wnem)/K*mask ; af = (y@Wcat)*mask ----------
#define O_AL 2176
#define O_BH 4352
#define O_BL 6528
#define O_YH 8704
#define O_YL 17408
#define FUSED_SMEM (26112*4)    // 104448 B

__global__ __launch_bounds__(256, 2)
void gemm_fused(const float* __restrict__ A,          // g_M [32768][384]
                const float* __restrict__ Wn,         // W_nem [384][128]
                const __nv_bfloat16* __restrict__ Wch,// [256][128]
                const __nv_bfloat16* __restrict__ Wcl,
                const float* __restrict__ maskrow,
                float* __restrict__ AF)               // [32768][256]
{
    extern __shared__ uint32_t sm[];
#define AH2(b,kp,x) sm[        (b)*1088 + (kp)*136 + (x)]
#define AL2(b,kp,x) sm[O_AL  + (b)*1088 + (kp)*136 + (x)]
#define BH2(b,kp,x) sm[O_BH  + (b)*1088 + (kp)*136 + (x)]
#define BL2(b,kp,x) sm[O_BL  + (b)*1088 + (kp)*136 + (x)]
#define YH(kp,x)    sm[O_YH  + (kp)*136 + (x)]
#define YL(kp,x)    sm[O_YL  + (kp)*136 + (x)]

    int tid  = threadIdx.x;
    int lane = tid & 31;
    int wid  = tid >> 5;
    int warp_m = wid >> 2;          // 0..1 -> m 0/64
    int warp_n = wid & 3;           // 0..3 -> n 0/32/64/96
    int row0 = blockIdx.x * 128;
    int r4 = lane >> 2, c4 = lane & 3;

    int a_r = tid >> 2;
    int a_c = (tid & 3) * 4;
    int b_c  = tid & 127;
    int b_kg = tid >> 7;

    float4 av0, av1;
    float  bv[8];

    float acc[4][4][4];
#pragma unroll
    for (int i = 0; i < 4; i++)
#pragma unroll
        for (int j = 0; j < 4; j++)
#pragma unroll
            for (int e = 0; e < 4; e++) acc[i][j][e] = 0.0f;

    // ---------------- GEMM1 mainloop (K = 384), single sync per chunk ----------------
    auto load_regs1 = [&](int kk) {
        av0 = *(const float4*)(A + (size_t)(row0 + a_r)*MDIM + kk + a_c);
        av1 = *(const float4*)(A + (size_t)(row0 + 64 + a_r)*MDIM + kk + a_c);
#pragma unroll
        for (int e = 0; e < 8; e++)
            bv[e] = Wn[(size_t)(kk + b_kg*8 + e)*Fc + b_c];
    };
    auto store_tile1 = [&](int buf) {
        int ac2 = a_c >> 1;
        uint32_t h, l;
        split2(av0.x, av0.y, h, l); AH2(buf, ac2,   a_r)    = h; AL2(buf, ac2,   a_r)    = l;
        split2(av0.z, av0.w, h, l); AH2(buf, ac2+1, a_r)    = h; AL2(buf, ac2+1, a_r)    = l;
        split2(av1.x, av1.y, h, l); AH2(buf, ac2,   a_r+64) = h; AL2(buf, ac2,   a_r+64) = l;
        split2(av1.z, av1.w, h, l); AH2(buf, ac2+1, a_r+64) = h; AL2(buf, ac2+1, a_r+64) = l;
#pragma unroll
        for (int p = 0; p < 4; p++) {
            split2(bv[2*p], bv[2*p+1], h, l);
            BH2(buf, b_kg*4 + p, b_c) = h;
            BL2(buf, b_kg*4 + p, b_c) = l;
        }
    };

    const int T1 = MDIM >> 4;       // 24
    load_regs1(0);
    store_tile1(0);
    __syncthreads();

    for (int t = 0; t < T1; t++) {
        int buf = t & 1;
        if (t + 1 < T1) load_regs1((t + 1) << 4);

        uint32_t bh[4][2], bl[4][2];
#pragma unroll
        for (int j = 0; j < 4; j++) {
            int n = warp_n*32 + j*8 + r4;
            bh[j][0] = BH2(buf, c4,   n);  bh[j][1] = BH2(buf, c4+4, n);
            bl[j][0] = BL2(buf, c4,   n);  bl[j][1] = BL2(buf, c4+4, n);
        }
#pragma unroll
        for (int i = 0; i < 4; i++) {
            int m = warp_m*64 + i*16 + r4;
            uint32_t ah[4], al[4];
            ah[0] = AH2(buf, c4,   m); ah[1] = AH2(buf, c4,   m+8);
            ah[2] = AH2(buf, c4+4, m); ah[3] = AH2(buf, c4+4, m+8);
            al[0] = AL2(buf, c4,   m); al[1] = AL2(buf, c4,   m+8);
            al[2] = AL2(buf, c4+4, m); al[3] = AL2(buf, c4+4, m+8);
#pragma unroll
            for (int j = 0; j < 4; j++) {
                mma_bf16(acc[i][j], ah, bh[j]);
                mma_bf16(acc[i][j], ah, bl[j]);
                mma_bf16(acc[i][j], al, bh[j]);
            }
        }
        // write NEXT tile into the other buffer; its last readers finished
        // before the previous barrier -> one sync per chunk is sufficient.
        if (t + 1 < T1) store_tile1((t + 1) & 1);
        __syncthreads();
    }

    // ---------------- stage y (masked, scaled) into smem split planes ----------------
    const float inv_k = 1.0f/(float)Kc;
#pragma unroll
    for (int i = 0; i < 4; i++) {
        int rl = warp_m*64 + i*16 + r4;
        float mlo = maskrow[row0 + rl]     * inv_k;
        float mhi = maskrow[row0 + rl + 8] * inv_k;
#pragma unroll
        for (int j = 0; j < 4; j++) {
            int kp = warp_n*16 + j*4 + c4;
            uint32_t h, l;
            split2(acc[i][j][0]*mlo, acc[i][j][1]*mlo, h, l);
            YH(kp, rl) = h;  YL(kp, rl) = l;
            split2(acc[i][j][2]*mhi, acc[i][j][3]*mhi, h, l);
            YH(kp, rl+8) = h;  YL(kp, rl+8) = l;
        }
    }
    __syncthreads();

    // ---------------- GEMM2: af[:, nh*128 .. ] = y @ WcatT (K = 128) ----------------
    uint4 vWh, vWl;
    auto load_regs2 = [&](int kk, int nh) {
        size_t off = (size_t)(nh*128 + b_c)*Fc + kk + b_kg*8;
        vWh = *(const uint4*)(Wch + off);
        vWl = *(const uint4*)(Wcl + off);
    };
    auto store_tile2 = [&](int buf) {
        BH2(buf, b_kg*4+0, b_c) = vWh.x;  BL2(buf, b_kg*4+0, b_c) = vWl.x;
        BH2(buf, b_kg*4+1, b_c) = vWh.y;  BL2(buf, b_kg*4+1, b_c) = vWl.y;
        BH2(buf, b_kg*4+2, b_c) = vWh.z;  BL2(buf, b_kg*4+2, b_c) = vWl.z;
        BH2(buf, b_kg*4+3, b_c) = vWh.w;  BL2(buf, b_kg*4+3, b_c) = vWl.w;
    };

    for (int nh = 0; nh < 2; nh++) {
#pragma unroll
        for (int i = 0; i < 4; i++)
#pragma unroll
            for (int j = 0; j < 4; j++)
#pragma unroll
                for (int e = 0; e < 4; e++) acc[i][j][e] = 0.0f;

        load_regs2(0, nh);
        store_tile2(0);
        __syncthreads();

        const int T2 = Fc >> 4;     // 8
        for (int t = 0; t < T2; t++) {
            int buf = t & 1;
            if (t + 1 < T2) load_regs2((t + 1) << 4, nh);

            uint32_t bh[4][2], bl[4][2];
#pragma unroll
            for (int j = 0; j < 4; j++) {
                int n = warp_n*32 + j*8 + r4;
                bh[j][0] = BH2(buf, c4,   n);  bh[j][1] = BH2(buf, c4+4, n);
                bl[j][0] = BL2(buf, c4,   n);  bl[j][1] = BL2(buf, c4+4, n);
            }
            int kb = t*8;
#pragma unroll
            for (int i = 0; i < 4; i++) {
                int m = warp_m*64 + i*16 + r4;
                uint32_t ah[4], al[4];
                ah[0] = YH(kb + c4,   m); ah[1] = YH(kb + c4,   m+8);
                ah[2] = YH(kb + c4+4, m); ah[3] = YH(kb + c4+4, m+8);
                al[0] = YL(kb + c4,   m); al[1] = YL(kb + c4,   m+8);
                al[2] = YL(kb + c4+4, m); al[3] = YL(kb + c4+4, m+8);
#pragma unroll
                for (int j = 0; j < 4; j++) {
                    mma_bf16(acc[i][j], ah, bh[j]);
                    mma_bf16(acc[i][j], ah, bl[j]);
                    mma_bf16(acc[i][j], al, bh[j]);
                }
            }
            if (t + 1 < T2) store_tile2((t + 1) & 1);
            __syncthreads();
        }

        // epilogue: af columns nh*128 + ...
#pragma unroll
        for (int i = 0; i < 4; i++) {
            int rlo = row0 + warp_m*64 + i*16 + r4;
            float mlo = maskrow[rlo];
            float mhi = maskrow[rlo+8];
#pragma unroll
            for (int j = 0; j < 4; j++) {
                int c = nh*128 + warp_n*32 + j*8 + c4*2;
                *(float2*)(AF + (size_t)rlo*(2*Dc) + c)     = make_float2(acc[i][j][0]*mlo, acc[i][j][1]*mlo);
                *(float2*)(AF + (size_t)(rlo+8)*(2*Dc) + c) = make_float2(acc[i][j][2]*mhi, acc[i][j][3]*mhi);
            }
        }
    }
#undef AH2
#undef AL2
#undef BH2
#undef BL2
#undef YH
#undef YL
}

// ---------------- K4: per-AA masked softmax pooling ----------------
__global__ void k4_pool(const int*  __restrict__ aa_nb_idx,
                        const int*  __restrict__ seq_idx_atom,
                        const int*  __restrict__ seq_idx_aa,
                        const float* __restrict__ mask_aa)
{
    int bm = blockIdx.x;            // 0..NAAT-1
    int b  = bm / NAAc;
    int d  = threadIdx.x;           // 0..127

    __shared__ int   s_ag[KNCc];
    __shared__ float s_gm[KNCc];
    __shared__ float s_mask[KNCc];

    if (d < KNCc) {
        int nb = aa_nb_idx[(size_t)bm*KNCc + d];
        int ag = b*NAc + nb;
        s_ag[d] = ag;
        float mnb = g_masky[ag];
        s_mask[d] = mnb;
        int sq = seq_idx_atom[ag];
        int sa = seq_idx_aa[bm];
        s_gm[d] = (sq == sa) ? mnb : 0.0f;
    }
    __syncthreads();

    float logit[KNCc];
    float mx = -3.0e38f;
#pragma unroll
    for (int k = 0; k < KNCc; k++) {
        float att = g_af[(size_t)s_ag[k]*(2*Dc) + d];
        float l = (s_mask[k] > 0.0f) ? att : -1.0e9f;
        logit[k] = l;
        mx = fmaxf(mx, l);
    }
    float e[KNCc];
    float se = 0.0f;
#pragma unroll
    for (int k = 0; k < KNCc; k++) { e[k] = __expf(logit[k]-mx); se += e[k]; }
    float inv_se = 1.0f/se;
    float w[KNCc];
    float sw = 0.0f;
#pragma unroll
    for (int k = 0; k < KNCc; k++) { w[k] = e[k]*inv_se*s_gm[k]; sw += w[k]; }
    float inv_den = 1.0f/(sw + 1e-8f);
    float pooled = 0.0f;
#pragma unroll
    for (int k = 0; k < KNCc; k++)
        pooled += (w[k]*inv_den) * g_af[(size_t)s_ag[k]*(2*Dc) + Dc + d];

    pooled *= mask_aa[bm];
    g_pooled[(size_t)bm*Dc + d] = pooled;
}

// ---------------- K5: masked batch-norm statistics ----------------
__global__ void k5_stats(const float* __restrict__ mask_aa)
{
    int d = blockIdx.x;             // 0..127
    int tid = threadIdx.x;          // 256
    float s0 = 0.0f, s1 = 0.0f, s2 = 0.0f;
    for (int r = tid; r < NAAT; r += 256) {
        float m = mask_aa[r];
        float p = g_pooled[(size_t)r*Dc + d];
        s0 += m;
        s1 += m*p;
        s2 += m*p*p;
    }
    __shared__ float sh0[256], sh1[256], sh2[256];
    sh0[tid] = s0; sh1[tid] = s1; sh2[tid] = s2;
    __syncthreads();
    for (int s = 128; s > 0; s >>= 1) {
        if (tid < s) {
            sh0[tid] += sh0[tid+s];
            sh1[tid] += sh1[tid+s];
            sh2[tid] += sh2[tid+s];
        }
        __syncthreads();
    }
    if (tid == 0) {
        float n = sh0[0] + 1e-8f;
        float mean = sh1[0]/n;
        float var = (sh2[0] - 2.0f*mean*sh1[0] + mean*mean*sh0[0])/n;
        g_mean[d] = mean;
        g_inv[d]  = rsqrtf(var + 1e-5f);
    }
}

// ---------------- K6: normalize + relu + write outputs ----------------
__global__ void k6_out(const float* __restrict__ gamma,
                       const float* __restrict__ beta,
                       const float* __restrict__ mask_aa,
                       float* __restrict__ out, int out_size)
{
    int idx = blockIdx.x * blockDim.x + threadIdx.x;
    const int total = NAAT*Dc;
    if (idx < total) {
        int d = idx & (Dc-1);
        int r = idx >> 7;
        float p = g_pooled[idx];
        float v = (gamma[d]*(p - g_mean[d])*g_inv[d] + beta[d]) * mask_aa[r];
        out[idx] = fmaxf(v, 0.0f);
    }
    if (idx < NAAT && total + idx < out_size) {
        out[total + idx] = mask_aa[idx];
    }
}

// ---------------- launch ----------------
extern "C" void kernel_launch(void* const* d_in, const int* in_sizes, int n_in,
                              void* d_out, int out_size)
{
    const float* point_clouds  = (const float*)d_in[0];
    const float* mask_atom     = (const float*)d_in[1];
    const float* mask_aa       = (const float*)d_in[2];
    const float* attr_table    = (const float*)d_in[3];
    const float* gauss_centers = (const float*)d_in[4];
    const float* W_nem         = (const float*)d_in[5];
    const float* W_att         = (const float*)d_in[6];
    const float* W_feat        = (const float*)d_in[7];
    const float* bn_gamma      = (const float*)d_in[8];
    const float* bn_beta       = (const float*)d_in[9];
    const int*   frame_idx     = (const int*)d_in[10];
    const int*   attr_idx      = (const int*)d_in[11];
    const int*   nb_idx        = (const int*)d_in[12];
    const int*   seq_idx_atom  = (const int*)d_in[13];
    const int*   seq_idx_aa    = (const int*)d_in[14];
    const int*   aa_nb_idx     = (const int*)d_in[15];
    float* out = (float*)d_out;

    float *pM, *pAF, *pMask;
    __nv_bfloat16 *pWch, *pWcl;
    cudaGetSymbolAddress((void**)&pM,   g_M);
    cudaGetSymbolAddress((void**)&pAF,  g_af);
    cudaGetSymbolAddress((void**)&pMask, g_masky);
    cudaGetSymbolAddress((void**)&pWch, g_Wch);
    cudaGetSymbolAddress((void**)&pWcl, g_Wcl);

    cudaFuncSetAttribute(gemm_fused, cudaFuncAttributeMaxDynamicSharedMemorySize, FUSED_SMEM);

    // K0 + weight prep
    k0_prep<<<(NATOM+255)/256, 256>>>(point_clouds, mask_atom, attr_table, frame_idx, attr_idx);
    kWt<<<(2*Dc*Fc+255)/256, 256>>>(W_att, W_feat);

    // K1: build M
    k1_buildM<<<(NATOM*32)/256, 256>>>(point_clouds, frame_idx, nb_idx, gauss_centers);

    // Fused GEMM1+GEMM2
    gemm_fused<<<NATOM/128, 256, FUSED_SMEM>>>(pM, W_nem, pWch, pWcl, pMask, pAF);

    // K4: pooled
    k4_pool<<<NAAT, Dc>>>(aa_nb_idx, seq_idx_atom, seq_idx_aa, mask_aa);

    // K5: batch-norm stats
    k5_stats<<<Dc, 256>>>(mask_aa);

    // K6: outputs
    k6_out<<<(NAAT*Dc + 255)/256, 256>>>(bn_gamma, bn_beta, mask_aa, out, out_size);
}